// round 7
// baseline (speedup 1.0000x reference)
#include <cuda_runtime.h>
#include <cuda_bf16.h>

// Problem constants
#define NB    4
#define NC    2000      // curves per batch
#define NLS   2000      // line samples per batch
#define NS    4000      // surfaces per batch
#define NF    8000      // faces per batch
#define NTS   26000     // triangle samples per batch
#define NPT   (NC + NLS + NS + NTS)   // 34000 points per batch
#define NPTOT (NB * NPT)              // 136000 points total
#define OG    258       // occ grid edge (256 + 2*2 pad - 3 + 1)
#define OGSQ  (OG * OG)                        // 66564 (divisible by 4)
#define X_ELEMS   (NB * NPT * 3)               // 408000
#define OCC_PER_B ((long)OG * OGSQ)            // 17,173,512
#define OCC_ELEMS (NB * OCC_PER_B)             // 68,669,448

// Scratch: packed voxel coords per point (c0 | c1<<8 | c2<<16).
__device__ int g_coords[NPTOT];

// ---------------------------------------------------------------------------
// Kernel 1: one thread per point. Computes the point with the exact f32 op
// order of the reference (no FMA contraction), writes x, writes packed coord.
// ---------------------------------------------------------------------------
__device__ __forceinline__ int cube_coord(float p) {
    float t = __fadd_rn(__fmul_rn(p, 256.0f), 128.5f);
    t = fminf(255.0f, fmaxf(0.0f, t));
    return (int)t;   // t >= 0 so truncation == floor
}

__global__ void points_kernel(const float* __restrict__ curves,
                              const float* __restrict__ surfaces,
                              const float* __restrict__ t_line,
                              const float* __restrict__ uv,
                              const int*   __restrict__ lines_array,
                              const int*   __restrict__ faces_array,
                              const int*   __restrict__ line_choice,
                              const int*   __restrict__ tri_choice,
                              float* __restrict__ out) {
    int idx = blockIdx.x * blockDim.x + threadIdx.x;
    if (idx >= NPTOT) return;
    int b = idx / NPT;
    int j = idx - b * NPT;

    float p0, p1, p2;

    if (j < NC) {
        // segment 0: curves passthrough
        const float* c = curves + ((long)(b * NC + j)) * 3;
        p0 = c[0]; p1 = c[1]; p2 = c[2];
    } else if (j < NC + NLS) {
        // segment 1: line interpolation  a + t*(b-a)
        int jj = j - NC;
        int lc = line_choice[b * NLS + jj];
        int s0 = lines_array[((long)(b * NC + lc)) * 2 + 0];
        int s1 = lines_array[((long)(b * NC + lc)) * 2 + 1];
        const float* A  = curves + ((long)(b * NC + s0)) * 3;
        const float* Bp = curves + ((long)(b * NC + s1)) * 3;
        float t = t_line[b * NLS + jj];
        p0 = __fadd_rn(A[0], __fmul_rn(t, __fsub_rn(Bp[0], A[0])));
        p1 = __fadd_rn(A[1], __fmul_rn(t, __fsub_rn(Bp[1], A[1])));
        p2 = __fadd_rn(A[2], __fmul_rn(t, __fsub_rn(Bp[2], A[2])));
    } else if (j < NC + NLS + NS) {
        // segment 2: surfaces passthrough
        int jj = j - (NC + NLS);
        const float* s = surfaces + ((long)(b * NS + jj)) * 3;
        p0 = s[0]; p1 = s[1]; p2 = s[2];
    } else {
        // segment 3: triangle barycentric sample
        int jj = j - (NC + NLS + NS);
        int tc = tri_choice[b * NTS + jj];
        const int* f = faces_array + ((long)(b * NF + tc)) * 3;
        const float* ta  = surfaces + ((long)(b * NS + f[0])) * 3;
        const float* tb  = surfaces + ((long)(b * NS + f[1])) * 3;
        const float* tcx = surfaces + ((long)(b * NS + f[2])) * 3;
        float u = uv[((long)(b * NTS + jj)) * 2 + 0];
        float v = uv[((long)(b * NTS + jj)) * 2 + 1];
        if (__fadd_rn(u, v) > 1.0f) {
            u = __fsub_rn(1.0f, u);
            v = __fsub_rn(1.0f, v);
        }
        // (ta + u*(tb-ta)) + v*(tc-ta), exact reference op order
        p0 = __fadd_rn(__fadd_rn(ta[0], __fmul_rn(u, __fsub_rn(tb[0], ta[0]))),
                       __fmul_rn(v, __fsub_rn(tcx[0], ta[0])));
        p1 = __fadd_rn(__fadd_rn(ta[1], __fmul_rn(u, __fsub_rn(tb[1], ta[1]))),
                       __fmul_rn(v, __fsub_rn(tcx[1], ta[1])));
        p2 = __fadd_rn(__fadd_rn(ta[2], __fmul_rn(u, __fsub_rn(tb[2], ta[2]))),
                       __fmul_rn(v, __fsub_rn(tcx[2], ta[2])));
    }

    // write x
    float* xo = out + ((long)idx) * 3;
    xo[0] = p0; xo[1] = p1; xo[2] = p2;

    // packed voxel coord for the occ kernel
    int c0 = cube_coord(p0);
    int c1 = cube_coord(p1);
    int c2 = cube_coord(p2);
    g_coords[idx] = c0 | (c1 << 8) | (c2 << 16);
}

// ---------------------------------------------------------------------------
// Kernel 2: fused zero + scatter with exclusive plane ownership.
// Block (b, p) owns output plane occ[b, p, :, :]:
//   phase 1: zero the plane (float4 streaming stores)
//   phase 2: scan the batch's packed coords (L1/L2-resident, coalesced) and
//            write the 3x3 rows of every point whose dilated block touches
//            this plane (c0 in {p-2, p-1, p}). These stores hit lines this
//            block just wrote -> L2-dirty hits, zero random DRAM traffic.
// __syncthreads between phases orders the CTA's global writes (cta-scope
// fence), and no other block ever writes this plane, so no races.
// Dilation == padded 3-maxpool of the one-hot grid; writes idempotent 1.0f;
// coords always in-bounds (c in [0,255] -> rows/cols in [0,257]).
// ---------------------------------------------------------------------------
__global__ void occ_kernel(float* __restrict__ out) {
    int b = blockIdx.x / OG;
    int p = blockIdx.x - b * OG;

    float* plane = out + X_ELEMS + (long)b * OCC_PER_B + (long)p * OGSQ;

    // phase 1: zero own plane
    float4* p4 = (float4*)plane;
    const int N4 = OGSQ / 4;  // 16641
    for (int i = threadIdx.x; i < N4; i += blockDim.x)
        p4[i] = make_float4(0.f, 0.f, 0.f, 0.f);
    __syncthreads();

    // phase 2: scatter rows of points touching this plane
    int lo = (p - 2 < 0) ? 0 : p - 2;
    int hi = (p < 255) ? p : 255;
    const int* coords = g_coords + b * NPT;
    for (int i = threadIdx.x; i < NPT; i += blockDim.x) {
        int packed = coords[i];
        int c0 = packed & 0xFF;
        if (c0 >= lo && c0 <= hi) {
            int c1 = (packed >> 8) & 0xFF;
            int c2 = (packed >> 16) & 0xFF;
            float* r = plane + c1 * OG + c2;
            r[0] = 1.0f; r[1] = 1.0f; r[2] = 1.0f;
            r += OG;
            r[0] = 1.0f; r[1] = 1.0f; r[2] = 1.0f;
            r += OG;
            r[0] = 1.0f; r[1] = 1.0f; r[2] = 1.0f;
        }
    }
}

extern "C" void kernel_launch(void* const* d_in, const int* in_sizes, int n_in,
                              void* d_out, int out_size) {
    // metadata order:
    // 0 imgs (unused), 1 curves, 2 surfaces, 3 t_line, 4 uv,
    // 5 lines_array, 6 faces_array, 7 indices_array (unused),
    // 8 line_choice, 9 tri_choice
    const float* curves      = (const float*)d_in[1];
    const float* surfaces    = (const float*)d_in[2];
    const float* t_line      = (const float*)d_in[3];
    const float* uv          = (const float*)d_in[4];
    const int*   lines_array = (const int*)d_in[5];
    const int*   faces_array = (const int*)d_in[6];
    const int*   line_choice = (const int*)d_in[8];
    const int*   tri_choice  = (const int*)d_in[9];
    float* out = (float*)d_out;

    int pb = (NPTOT + 255) / 256;
    points_kernel<<<pb, 256>>>(curves, surfaces, t_line, uv,
                               lines_array, faces_array,
                               line_choice, tri_choice, out);

    // fused zero+scatter: one block per (batch, output plane)
    occ_kernel<<<NB * OG, 256>>>(out);
}

// round 9
// speedup vs baseline: 1.0372x; 1.0372x over previous
#include <cuda_runtime.h>
#include <cuda_bf16.h>

// Problem constants
#define NB    4
#define NC    2000      // curves per batch
#define NLS   2000      // line samples per batch
#define NS    4000      // surfaces per batch
#define NF    8000      // faces per batch
#define NTS   26000     // triangle samples per batch
#define NPT   (NC + NLS + NS + NTS)   // 34000 points per batch
#define NPTOT (NB * NPT)              // 136000 points total
#define OG    258       // occ grid edge (256 + 2*2 pad - 3 + 1)
#define OGSQ  (OG * OG)                        // 66564 (divisible by 4)
#define X_ELEMS   (NB * NPT * 3)               // 408000
#define OCC_PER_B ((long)OG * OGSQ)            // 17,173,512
#define OCC_ELEMS (NB * OCC_PER_B)             // 68,669,448

#define NPLANES (NB * OG)   // 1032
#define PCAP    4096        // per-plane list capacity (worst case ~700)

// Per-(batch,plane) bins: counts + entry lists (entry = c1<<8 | c2).
__device__ int g_bin_count[NPLANES];
__device__ int g_bin_list[NPLANES * PCAP];

// ---------------------------------------------------------------------------
// Kernel 0: clear the bin counters.
// ---------------------------------------------------------------------------
__global__ void zero_bins_kernel() {
    int i = blockIdx.x * blockDim.x + threadIdx.x;
    if (i < NPLANES) g_bin_count[i] = 0;
}

// ---------------------------------------------------------------------------
// Kernel 1: one thread per point. Computes the point with the exact f32 op
// order of the reference (no FMA contraction), writes x, bins the voxel
// coord into the 3 planes its dilated block touches.
// ---------------------------------------------------------------------------
__device__ __forceinline__ int cube_coord(float p) {
    float t = __fadd_rn(__fmul_rn(p, 256.0f), 128.5f);
    t = fminf(255.0f, fmaxf(0.0f, t));
    return (int)t;   // t >= 0 so truncation == floor
}

__global__ void points_kernel(const float* __restrict__ curves,
                              const float* __restrict__ surfaces,
                              const float* __restrict__ t_line,
                              const float* __restrict__ uv,
                              const int*   __restrict__ lines_array,
                              const int*   __restrict__ faces_array,
                              const int*   __restrict__ line_choice,
                              const int*   __restrict__ tri_choice,
                              float* __restrict__ out) {
    int idx = blockIdx.x * blockDim.x + threadIdx.x;
    if (idx >= NPTOT) return;
    int b = idx / NPT;
    int j = idx - b * NPT;

    float p0, p1, p2;

    if (j < NC) {
        // segment 0: curves passthrough
        const float* c = curves + ((long)(b * NC + j)) * 3;
        p0 = c[0]; p1 = c[1]; p2 = c[2];
    } else if (j < NC + NLS) {
        // segment 1: line interpolation  a + t*(b-a)
        int jj = j - NC;
        int lc = line_choice[b * NLS + jj];
        int s0 = lines_array[((long)(b * NC + lc)) * 2 + 0];
        int s1 = lines_array[((long)(b * NC + lc)) * 2 + 1];
        const float* A  = curves + ((long)(b * NC + s0)) * 3;
        const float* Bp = curves + ((long)(b * NC + s1)) * 3;
        float t = t_line[b * NLS + jj];
        p0 = __fadd_rn(A[0], __fmul_rn(t, __fsub_rn(Bp[0], A[0])));
        p1 = __fadd_rn(A[1], __fmul_rn(t, __fsub_rn(Bp[1], A[1])));
        p2 = __fadd_rn(A[2], __fmul_rn(t, __fsub_rn(Bp[2], A[2])));
    } else if (j < NC + NLS + NS) {
        // segment 2: surfaces passthrough
        int jj = j - (NC + NLS);
        const float* s = surfaces + ((long)(b * NS + jj)) * 3;
        p0 = s[0]; p1 = s[1]; p2 = s[2];
    } else {
        // segment 3: triangle barycentric sample
        int jj = j - (NC + NLS + NS);
        int tc = tri_choice[b * NTS + jj];
        const int* f = faces_array + ((long)(b * NF + tc)) * 3;
        const float* ta  = surfaces + ((long)(b * NS + f[0])) * 3;
        const float* tb  = surfaces + ((long)(b * NS + f[1])) * 3;
        const float* tcx = surfaces + ((long)(b * NS + f[2])) * 3;
        float u = uv[((long)(b * NTS + jj)) * 2 + 0];
        float v = uv[((long)(b * NTS + jj)) * 2 + 1];
        if (__fadd_rn(u, v) > 1.0f) {
            u = __fsub_rn(1.0f, u);
            v = __fsub_rn(1.0f, v);
        }
        // (ta + u*(tb-ta)) + v*(tc-ta), exact reference op order
        p0 = __fadd_rn(__fadd_rn(ta[0], __fmul_rn(u, __fsub_rn(tb[0], ta[0]))),
                       __fmul_rn(v, __fsub_rn(tcx[0], ta[0])));
        p1 = __fadd_rn(__fadd_rn(ta[1], __fmul_rn(u, __fsub_rn(tb[1], ta[1]))),
                       __fmul_rn(v, __fsub_rn(tcx[1], ta[1])));
        p2 = __fadd_rn(__fadd_rn(ta[2], __fmul_rn(u, __fsub_rn(tb[2], ta[2]))),
                       __fmul_rn(v, __fsub_rn(tcx[2], ta[2])));
    }

    // write x
    float* xo = out + ((long)idx) * 3;
    xo[0] = p0; xo[1] = p1; xo[2] = p2;

    // bin the voxel coord into the 3 planes touched by its dilation
    int c0 = cube_coord(p0);
    int c1 = cube_coord(p1);
    int c2 = cube_coord(p2);
    int entry = (c1 << 8) | c2;
    int base = b * OG + c0;
    #pragma unroll
    for (int d0 = 0; d0 < 3; d0++) {
        int plane = base + d0;                      // c0+d0 <= 257 < OG
        int slot = atomicAdd(&g_bin_count[plane], 1);
        if (slot < PCAP) g_bin_list[plane * PCAP + slot] = entry;
    }
}

// ---------------------------------------------------------------------------
// Kernel 2: fused zero + scatter with exclusive plane ownership.
// Block (b, p) owns output plane occ[b, p, :, :]:
//   phase 1: zero the plane (float4 streaming stores)
//   phase 2: process ONLY this plane's binned entries (~400) and write the
//            3x3-row dilation footprint. These stores hit lines this block
//            just wrote -> L2-dirty hits, no random DRAM traffic.
// __syncthreads orders the CTA's own global writes; no other block writes
// this plane, so no races. Writes idempotent 1.0f; coords always in-bounds.
// ---------------------------------------------------------------------------
__global__ void occ_kernel(float* __restrict__ out) {
    int b = blockIdx.x / OG;
    int p = blockIdx.x - b * OG;

    float* plane = out + X_ELEMS + (long)b * OCC_PER_B + (long)p * OGSQ;

    // phase 1: zero own plane
    float4* p4 = (float4*)plane;
    const int N4 = OGSQ / 4;  // 16641
    for (int i = threadIdx.x; i < N4; i += blockDim.x)
        p4[i] = make_float4(0.f, 0.f, 0.f, 0.f);
    __syncthreads();

    // phase 2: scatter this plane's binned entries
    int n = g_bin_count[blockIdx.x];
    if (n > PCAP) n = PCAP;
    const int* list = g_bin_list + blockIdx.x * PCAP;
    for (int i = threadIdx.x; i < n; i += blockDim.x) {
        int entry = list[i];
        int c1 = entry >> 8;
        int c2 = entry & 0xFF;
        float* r = plane + c1 * OG + c2;
        r[0] = 1.0f; r[1] = 1.0f; r[2] = 1.0f;
        r += OG;
        r[0] = 1.0f; r[1] = 1.0f; r[2] = 1.0f;
        r += OG;
        r[0] = 1.0f; r[1] = 1.0f; r[2] = 1.0f;
    }
}

extern "C" void kernel_launch(void* const* d_in, const int* in_sizes, int n_in,
                              void* d_out, int out_size) {
    // metadata order:
    // 0 imgs (unused), 1 curves, 2 surfaces, 3 t_line, 4 uv,
    // 5 lines_array, 6 faces_array, 7 indices_array (unused),
    // 8 line_choice, 9 tri_choice
    const float* curves      = (const float*)d_in[1];
    const float* surfaces    = (const float*)d_in[2];
    const float* t_line      = (const float*)d_in[3];
    const float* uv          = (const float*)d_in[4];
    const int*   lines_array = (const int*)d_in[5];
    const int*   faces_array = (const int*)d_in[6];
    const int*   line_choice = (const int*)d_in[8];
    const int*   tri_choice  = (const int*)d_in[9];
    float* out = (float*)d_out;

    zero_bins_kernel<<<(NPLANES + 255) / 256, 256>>>();

    int pb = (NPTOT + 255) / 256;
    points_kernel<<<pb, 256>>>(curves, surfaces, t_line, uv,
                               lines_array, faces_array,
                               line_choice, tri_choice, out);

    // fused zero+scatter: one block per (batch, output plane)
    occ_kernel<<<NB * OG, 256>>>(out);
}

// round 10
// speedup vs baseline: 1.5611x; 1.5052x over previous
#include <cuda_runtime.h>
#include <cuda_bf16.h>

// Problem constants
#define NB    4
#define NC    2000      // curves per batch
#define NLS   2000      // line samples per batch
#define NS    4000      // surfaces per batch
#define NF    8000      // faces per batch
#define NTS   26000     // triangle samples per batch
#define NPT   (NC + NLS + NS + NTS)   // 34000 points per batch
#define NPTOT (NB * NPT)              // 136000 points total
#define OG    258       // occ grid edge (256 + 2*2 pad - 3 + 1)
#define OGSQ  (OG * OG)                        // 66564
#define X_ELEMS   (NB * NPT * 3)               // 408000
#define OCC_PER_B ((long)OG * OGSQ)            // 17,173,512 (divisible by 4)
#define OCC_ELEMS (NB * OCC_PER_B)             // 68,669,448

// Scratch: packed voxel coords per point (c0 | c1<<8 | c2<<16).
__device__ int g_coords[NPTOT];

// ---------------------------------------------------------------------------
// Kernel 1: one thread per point. Computes the point with the exact f32 op
// order of the reference (no FMA contraction), writes x, writes packed coord.
// ---------------------------------------------------------------------------
__device__ __forceinline__ int cube_coord(float p) {
    float t = __fadd_rn(__fmul_rn(p, 256.0f), 128.5f);
    t = fminf(255.0f, fmaxf(0.0f, t));
    return (int)t;   // t >= 0 so truncation == floor
}

__global__ void points_kernel(const float* __restrict__ curves,
                              const float* __restrict__ surfaces,
                              const float* __restrict__ t_line,
                              const float* __restrict__ uv,
                              const int*   __restrict__ lines_array,
                              const int*   __restrict__ faces_array,
                              const int*   __restrict__ line_choice,
                              const int*   __restrict__ tri_choice,
                              float* __restrict__ out) {
    int idx = blockIdx.x * blockDim.x + threadIdx.x;
    if (idx >= NPTOT) return;
    int b = idx / NPT;
    int j = idx - b * NPT;

    float p0, p1, p2;

    if (j < NC) {
        // segment 0: curves passthrough
        const float* c = curves + ((long)(b * NC + j)) * 3;
        p0 = c[0]; p1 = c[1]; p2 = c[2];
    } else if (j < NC + NLS) {
        // segment 1: line interpolation  a + t*(b-a)
        int jj = j - NC;
        int lc = line_choice[b * NLS + jj];
        int s0 = lines_array[((long)(b * NC + lc)) * 2 + 0];
        int s1 = lines_array[((long)(b * NC + lc)) * 2 + 1];
        const float* A  = curves + ((long)(b * NC + s0)) * 3;
        const float* Bp = curves + ((long)(b * NC + s1)) * 3;
        float t = t_line[b * NLS + jj];
        p0 = __fadd_rn(A[0], __fmul_rn(t, __fsub_rn(Bp[0], A[0])));
        p1 = __fadd_rn(A[1], __fmul_rn(t, __fsub_rn(Bp[1], A[1])));
        p2 = __fadd_rn(A[2], __fmul_rn(t, __fsub_rn(Bp[2], A[2])));
    } else if (j < NC + NLS + NS) {
        // segment 2: surfaces passthrough
        int jj = j - (NC + NLS);
        const float* s = surfaces + ((long)(b * NS + jj)) * 3;
        p0 = s[0]; p1 = s[1]; p2 = s[2];
    } else {
        // segment 3: triangle barycentric sample
        int jj = j - (NC + NLS + NS);
        int tc = tri_choice[b * NTS + jj];
        const int* f = faces_array + ((long)(b * NF + tc)) * 3;
        const float* ta  = surfaces + ((long)(b * NS + f[0])) * 3;
        const float* tb  = surfaces + ((long)(b * NS + f[1])) * 3;
        const float* tcx = surfaces + ((long)(b * NS + f[2])) * 3;
        float u = uv[((long)(b * NTS + jj)) * 2 + 0];
        float v = uv[((long)(b * NTS + jj)) * 2 + 1];
        if (__fadd_rn(u, v) > 1.0f) {
            u = __fsub_rn(1.0f, u);
            v = __fsub_rn(1.0f, v);
        }
        // (ta + u*(tb-ta)) + v*(tc-ta), exact reference op order
        p0 = __fadd_rn(__fadd_rn(ta[0], __fmul_rn(u, __fsub_rn(tb[0], ta[0]))),
                       __fmul_rn(v, __fsub_rn(tcx[0], ta[0])));
        p1 = __fadd_rn(__fadd_rn(ta[1], __fmul_rn(u, __fsub_rn(tb[1], ta[1]))),
                       __fmul_rn(v, __fsub_rn(tcx[1], ta[1])));
        p2 = __fadd_rn(__fadd_rn(ta[2], __fmul_rn(u, __fsub_rn(tb[2], ta[2]))),
                       __fmul_rn(v, __fsub_rn(tcx[2], ta[2])));
    }

    // write x
    float* xo = out + ((long)idx) * 3;
    xo[0] = p0; xo[1] = p1; xo[2] = p2;

    // packed voxel coord for the scatter kernels
    int c0 = cube_coord(p0);
    int c1 = cube_coord(p1);
    int c2 = cube_coord(p2);
    g_coords[idx] = c0 | (c1 << 8) | (c2 << 16);
}

// ---------------------------------------------------------------------------
// Kernel 2: flat grid-stride zero of ONE batch's occ slab (68.7 MB).
// Chip-wide dense address sweep -> full DRAM streaming-write bandwidth
// (~6.4 TB/s measured in R4), and the slab lands resident in L2 (68.7 MB
// < 126 MB), which is what makes the following scatter cheap.
// ---------------------------------------------------------------------------
__global__ void zero_batch_kernel(float4* __restrict__ p) {
    const int n4 = (int)(OCC_PER_B / 4);       // 4,293,378
    int i = blockIdx.x * blockDim.x + threadIdx.x;
    if (i < n4) p[i] = make_float4(0.f, 0.f, 0.f, 0.f);
}

// ---------------------------------------------------------------------------
// Kernel 3: scatter for ONE batch. One thread per (point, d0, d1) — each
// writes one 3-float row of the dilated 3x3x3 block. Runs immediately after
// that batch's zero, so every touched line is still L2-resident (dirty):
// the stores are L2 partial-sector hits, no DRAM read-modify-write.
// Dilation == padded 3-maxpool of the one-hot grid; coords always in-bounds
// (c in [0,255] -> rows in [0,257]); writes idempotent 1.0f, so no races.
// ---------------------------------------------------------------------------
__global__ void scatter_batch_kernel(float* __restrict__ occ, int b) {
    int pidx = blockIdx.x * blockDim.x + threadIdx.x;
    if (pidx >= NPT) return;
    int r  = blockIdx.y;       // 0..8
    int d0 = r / 3;
    int d1 = r - d0 * 3;

    int packed = g_coords[b * NPT + pidx];     // coalesced; L2-hit across y
    int c0 = packed & 0xFF;
    int c1 = (packed >> 8) & 0xFF;
    int c2 = (packed >> 16) & 0xFF;

    float* row = occ + (long)(c0 + d0) * OGSQ + (long)(c1 + d1) * OG + c2;
    row[0] = 1.0f; row[1] = 1.0f; row[2] = 1.0f;
}

extern "C" void kernel_launch(void* const* d_in, const int* in_sizes, int n_in,
                              void* d_out, int out_size) {
    // metadata order:
    // 0 imgs (unused), 1 curves, 2 surfaces, 3 t_line, 4 uv,
    // 5 lines_array, 6 faces_array, 7 indices_array (unused),
    // 8 line_choice, 9 tri_choice
    const float* curves      = (const float*)d_in[1];
    const float* surfaces    = (const float*)d_in[2];
    const float* t_line      = (const float*)d_in[3];
    const float* uv          = (const float*)d_in[4];
    const int*   lines_array = (const int*)d_in[5];
    const int*   faces_array = (const int*)d_in[6];
    const int*   line_choice = (const int*)d_in[8];
    const int*   tri_choice  = (const int*)d_in[9];
    float* out = (float*)d_out;

    int pb = (NPTOT + 255) / 256;
    points_kernel<<<pb, 256>>>(curves, surfaces, t_line, uv,
                               lines_array, faces_array,
                               line_choice, tri_choice, out);

    // per-batch: zero slab (lands in L2) then scatter into the resident slab
    const int n4 = (int)(OCC_PER_B / 4);
    int zb = (n4 + 255) / 256;
    int sb = (NPT + 255) / 256;          // 133
    for (int b = 0; b < NB; b++) {
        float* occ_b = out + X_ELEMS + (long)b * OCC_PER_B;
        zero_batch_kernel<<<zb, 256>>>((float4*)occ_b);
        dim3 sg(sb, 9, 1);
        scatter_batch_kernel<<<sg, 256>>>(occ_b, b);
    }
}